// round 4
// baseline (speedup 1.0000x reference)
#include <cuda_runtime.h>
#include <cuda_fp16.h>
#include <math.h>

#define N_IMG 128
#define N_ANG 285
#define N_DET 183
#define N_T   384

#define PITCH2 133          // smem row pitch in half2 entries
#define PROWS  131
#define SMEM_H2    (PROWS * PITCH2)
#define SMEM_BYTES (SMEM_H2 * 4)

#define THREADS 384         // 2 sub-segs x 192 threads (>=183 detectors)
#define NSPLIT  3           // k-range thirds across grid.z
#define SEGLEN  64          // per-thread k count: 384 / (3*2)

__global__ __launch_bounds__(THREADS)
void radon_fwd_kernel(const float* __restrict__ x, float* __restrict__ out) {
    extern __shared__ __half2 simg[];
    __shared__ float2 part[THREADS];
    __shared__ double geo[6];   // a0, c0, a1, c1, is0, is1
    __shared__ float  stf[2];   // (float)st0, (float)st1

    const int tid = threadIdx.x;
    const int ang = blockIdx.x;
    const int bp  = blockIdx.y;         // batch pair (0..3)
    const int thd = blockIdx.z;         // k-third (0..2)

    const double RHO = 20.0 * sqrt(2.0);
    const double DX  = 0.3125;
    const double DT  = 2.0 * RHO / (double)N_T;
    const float  SCALE = (float)(DT / 12.0);

    if (tid == 0) {
        double a = ((double)ang + 0.5) * M_PI / (double)N_ANG;
        double dsin = sin(a), dcos = cos(a);
        double tb = -RHO + 0.5 * DT;
        double st0 = DT * dcos / DX;
        double st1 = DT * dsin / DX;
        geo[0] = -dsin / DX;                    // row coeff on s
        geo[1] = (tb * dcos + 20.0) / DX + 0.5; // row base (padded)
        geo[2] =  dcos / DX;                    // col coeff on s
        geo[3] = (tb * dsin + 20.0) / DX + 0.5; // col base (padded)
        geo[4] = (fabs(st0) < 1e-9) ? 0.0 : 1.0 / st0;
        geo[5] = (fabs(st1) < 1e-9) ? 0.0 : 1.0 / st1;
        stf[0] = (float)st0;
        stf[1] = (float)st1;
    }

    // Fill interior (rows 1..128, cols 1..128) with interleaved batch pair
    const float* iA = x + (size_t)(2 * bp) * N_IMG * N_IMG;
    const float* iB = iA + N_IMG * N_IMG;
    for (int i = tid; i < N_IMG * N_IMG; i += THREADS) {
        int r = i >> 7;
        int c = i & 127;
        simg[(r + 1) * PITCH2 + (c + 1)] = __floats2half2_rn(iA[i], iB[i]);
    }
    // Zero only the readable border ring: rows 0 & 129 (cols 0..129),
    // cols 0 & 129 (rows 1..128). EPS-clip guarantees nothing else is read.
    {
        const __half2 z = __floats2half2_rn(0.0f, 0.0f);
        for (int c = tid; c < 130; c += THREADS) {
            simg[c] = z;
            simg[129 * PITCH2 + c] = z;
        }
        for (int r = 1 + tid; r <= 128; r += THREADS) {
            simg[r * PITCH2] = z;
            simg[r * PITCH2 + 129] = z;
        }
    }
    __syncthreads();

    const int det = tid % 192;
    const int seg = tid / 192;          // 0..1

    float accA = 0.0f, accB = 0.0f;

    if (det < N_DET) {
        double s = -RHO + ((double)det + 0.5) * (2.0 * RHO / (double)N_DET);
        double b0d = fma(s, geo[0], geo[1]);   // padded row @ k=0
        double b1d = fma(s, geo[2], geo[3]);   // padded col @ k=0

        const double EPS = 2e-4;
        int klo = thd * 2 * SEGLEN + seg * SEGLEN;
        int khi = klo + SEGLEN;
        {
            double bases[2] = {b0d, b1d};
            #pragma unroll
            for (int ax = 0; ax < 2; ++ax) {
                double bs = bases[ax], is = geo[4 + ax];
                if (is == 0.0) {
                    if (bs < EPS || bs > 129.0 - EPS) klo = khi;
                } else {
                    double t0 = (EPS - bs) * is;
                    double t1 = ((129.0 - EPS) - bs) * is;
                    double lo = fmin(t0, t1), hi = fmax(t0, t1);
                    int kl = (int)ceil(lo);
                    int kh = (int)floor(hi) + 1;   // exclusive
                    if (kl > klo) klo = kl;
                    if (kh < khi) khi = kh;
                }
            }
        }

        const float b0 = (float)b0d, s0 = stf[0];
        const float b1 = (float)b1d, s1 = stf[1];

        float kf = (float)klo;
        #pragma unroll 4
        for (int k = klo; k < khi; ++k, kf += 1.0f) {
            float f0 = fmaf(kf, s0, b0);
            float f1 = fmaf(kf, s1, b1);
            float fl0 = floorf(f0);
            float fl1 = floorf(f1);
            float a  = f0 - fl0;
            float bb = f1 - fl1;
            int boff = (int)fmaf(fl0, (float)(PITCH2 * 4), fl1 * 4.0f);
            const __half2* p = (const __half2*)((const char*)simg + boff);
            __half2 v00 = p[0];
            __half2 v01 = p[1];
            __half2 v10 = p[PITCH2];
            __half2 v11 = p[PITCH2 + 1];
            __half2 b2 = __float2half2_rn(bb);
            __half2 a2 = __float2half2_rn(a);
            __half2 top = __hfma2(b2, __hsub2(v01, v00), v00);
            __half2 bot = __hfma2(b2, __hsub2(v11, v10), v10);
            __half2 r2  = __hfma2(a2, __hsub2(bot, top), top);
            float2 rf = __half22float2(r2);
            accA += rf.x;
            accB += rf.y;
        }
    }

    part[tid] = make_float2(accA, accB);
    __syncthreads();

    if (tid < N_DET) {
        float2 p0 = part[tid];
        float2 p1 = part[tid + 192];
        float rA = (p0.x + p1.x) * SCALE;
        float rB = (p0.y + p1.y) * SCALE;
        size_t baseA = ((size_t)(2 * bp)     * N_ANG + ang) * N_DET + tid;
        size_t baseB = ((size_t)(2 * bp + 1) * N_ANG + ang) * N_DET + tid;
        atomicAdd(&out[baseA], rA);
        atomicAdd(&out[baseB], rB);
    }
}

extern "C" void kernel_launch(void* const* d_in, const int* in_sizes, int n_in,
                              void* d_out, int out_size) {
    const float* x = (const float*)d_in[0];
    float* out = (float*)d_out;
    cudaFuncSetAttribute(radon_fwd_kernel,
                         cudaFuncAttributeMaxDynamicSharedMemorySize, SMEM_BYTES);
    cudaMemsetAsync(d_out, 0, (size_t)out_size * sizeof(float), 0);
    dim3 grid(N_ANG, 4, NSPLIT);
    radon_fwd_kernel<<<grid, THREADS, SMEM_BYTES>>>(x, out);
}

// round 5
// speedup vs baseline: 1.8603x; 1.8603x over previous
#include <cuda_runtime.h>
#include <cuda_fp16.h>
#include <math.h>

#define N_IMG 128
#define N_ANG 285
#define N_DET 183
#define N_T   384

#define PITCH2 133
#define PROWS  131
#define SMEM_H2    (PROWS * PITCH2)
#define SMEM_BYTES (SMEM_H2 * 4)

#define THREADS 384         // 2 k-segments x 192 threads

__global__ __launch_bounds__(THREADS)
void radon_fwd_kernel(const float* __restrict__ x, float* __restrict__ out) {
    extern __shared__ __half2 simg[];
    __shared__ float2 part[THREADS];
    __shared__ double geo[6];   // row coeff/base, col coeff/base, 1/st0, 1/st1
    __shared__ float  stf[2];

    const int tid = threadIdx.x;
    const int ang = blockIdx.x;
    const int bp  = blockIdx.y;

    const double RHO = 20.0 * sqrt(2.0);
    const double DX  = 0.3125;
    const double DT  = 2.0 * RHO / (double)N_T;
    const float  SCALE = (float)(DT / 12.0);

    if (tid == 0) {
        double a = ((double)ang + 0.5) * M_PI / (double)N_ANG;
        double dsin = sin(a), dcos = cos(a);
        double tb = -RHO + 0.5 * DT;
        double st0 = DT * dcos / DX;
        double st1 = DT * dsin / DX;
        geo[0] = -dsin / DX;
        geo[1] = (tb * dcos + 20.0) / DX + 0.5;
        geo[2] =  dcos / DX;
        geo[3] = (tb * dsin + 20.0) / DX + 0.5;
        geo[4] = (fabs(st0) < 1e-9) ? 0.0 : 1.0 / st0;
        geo[5] = (fabs(st1) < 1e-9) ? 0.0 : 1.0 / st1;
        stf[0] = (float)st0;
        stf[1] = (float)st1;
    }

    // Interior fill, vectorized: 4 pixels per thread-iteration
    const float4* iA4 = (const float4*)(x + (size_t)(2 * bp) * N_IMG * N_IMG);
    const float4* iB4 = (const float4*)(x + (size_t)(2 * bp + 1) * N_IMG * N_IMG);
    for (int q = tid; q < N_IMG * N_IMG / 4; q += THREADS) {
        float4 a4 = iA4[q];
        float4 b4 = iB4[q];
        int r = q >> 5;            // q*4 / 128
        int c = (q & 31) << 2;
        __half2* dst = &simg[(r + 1) * PITCH2 + (c + 1)];
        dst[0] = __floats2half2_rn(a4.x, b4.x);
        dst[1] = __floats2half2_rn(a4.y, b4.y);
        dst[2] = __floats2half2_rn(a4.z, b4.z);
        dst[3] = __floats2half2_rn(a4.w, b4.w);
    }
    // Zero only the readable border ring (EPS-clip keeps reads in rows/cols 0..129)
    {
        const __half2 z = __floats2half2_rn(0.0f, 0.0f);
        for (int c = tid; c < 130; c += THREADS) {
            simg[c] = z;
            simg[129 * PITCH2 + c] = z;
        }
        for (int r = 1 + tid; r <= 128; r += THREADS) {
            simg[r * PITCH2] = z;
            simg[r * PITCH2 + 129] = z;
        }
    }
    __syncthreads();

    const int det = tid % 192;
    const int seg = tid / 192;

    float accA = 0.0f, accB = 0.0f;

    if (det < N_DET) {
        double s = -RHO + ((double)det + 0.5) * (2.0 * RHO / (double)N_DET);
        double b0d = fma(s, geo[0], geo[1]);
        double b1d = fma(s, geo[2], geo[3]);

        const double EPS = 2e-4;
        int klo = seg * 192;
        int khi = klo + 192;
        {
            double bases[2] = {b0d, b1d};
            #pragma unroll
            for (int ax = 0; ax < 2; ++ax) {
                double bs = bases[ax], is = geo[4 + ax];
                if (is == 0.0) {
                    if (bs < EPS || bs > 129.0 - EPS) klo = khi;
                } else {
                    double t0 = (EPS - bs) * is;
                    double t1 = ((129.0 - EPS) - bs) * is;
                    double lo = fmin(t0, t1), hi = fmax(t0, t1);
                    int kl = (int)ceil(lo);
                    int kh = (int)floor(hi) + 1;
                    if (kl > klo) klo = kl;
                    if (kh < khi) khi = kh;
                }
            }
        }
        if (khi < klo) khi = klo;

        const float b0 = (float)b0d, s0 = stf[0];
        const float b1 = (float)b1d, s1 = stf[1];
        const float b0p = b0 + s0;          // base for the k+1 sample
        const float b1p = b1 + s1;

        int n = khi - klo;                  // samples this thread
        float kf = (float)klo;

        #define SAMPLE(F0, F1, OUT2)                                           \
        {                                                                      \
            float fl0 = floorf(F0);                                            \
            float fl1 = floorf(F1);                                            \
            float fa  = (F0) - fl0;                                            \
            float fb  = (F1) - fl1;                                            \
            int boff = (int)fmaf(fl0, (float)(PITCH2 * 4), fl1 * 4.0f);        \
            const __half2* p = (const __half2*)((const char*)simg + boff);     \
            __half2 v00 = p[0];                                                \
            __half2 v01 = p[1];                                                \
            __half2 v10 = p[PITCH2];                                           \
            __half2 v11 = p[PITCH2 + 1];                                       \
            __half2 b2 = __float2half2_rn(fb);                                 \
            __half2 a2 = __float2half2_rn(fa);                                 \
            __half2 top = __hfma2(b2, __hsub2(v01, v00), v00);                 \
            __half2 bot = __hfma2(b2, __hsub2(v11, v10), v10);                 \
            OUT2 = __hfma2(a2, __hsub2(bot, top), top);                        \
        }

        int npair = n >> 1;
        #pragma unroll 4
        for (int it = 0; it < npair; ++it, kf += 2.0f) {
            float f0a = fmaf(kf, s0, b0);
            float f1a = fmaf(kf, s1, b1);
            float f0b = fmaf(kf, s0, b0p);
            float f1b = fmaf(kf, s1, b1p);
            __half2 ra, rb;
            SAMPLE(f0a, f1a, ra)
            SAMPLE(f0b, f1b, rb)
            __half2 rs = __hadd2(ra, rb);
            float2 rf = __half22float2(rs);
            accA += rf.x;
            accB += rf.y;
        }
        if (n & 1) {
            float f0a = fmaf(kf, s0, b0);
            float f1a = fmaf(kf, s1, b1);
            __half2 ra;
            SAMPLE(f0a, f1a, ra)
            float2 rf = __half22float2(ra);
            accA += rf.x;
            accB += rf.y;
        }
        #undef SAMPLE
    }

    part[tid] = make_float2(accA, accB);
    __syncthreads();

    if (tid < N_DET) {
        float2 p0 = part[tid];
        float2 p1 = part[tid + 192];
        float rA = (p0.x + p1.x) * SCALE;
        float rB = (p0.y + p1.y) * SCALE;
        size_t baseA = ((size_t)(2 * bp)     * N_ANG + ang) * N_DET + tid;
        size_t baseB = ((size_t)(2 * bp + 1) * N_ANG + ang) * N_DET + tid;
        out[baseA] = rA;
        out[baseB] = rB;
    }
}

extern "C" void kernel_launch(void* const* d_in, const int* in_sizes, int n_in,
                              void* d_out, int out_size) {
    const float* x = (const float*)d_in[0];
    float* out = (float*)d_out;
    cudaFuncSetAttribute(radon_fwd_kernel,
                         cudaFuncAttributeMaxDynamicSharedMemorySize, SMEM_BYTES);
    dim3 grid(N_ANG, 4);
    radon_fwd_kernel<<<grid, THREADS, SMEM_BYTES>>>(x, out);
}